// round 10
// baseline (speedup 1.0000x reference)
#include <cuda_runtime.h>
#include <cuda_bf16.h>
#include <math.h>
#include <stdint.h>

#define B_   128
#define S_   512
#define I_   512
#define H_   1024
#define O_   512
#define NCTA 128

// ---------------------------------------------------------------------------
// device globals (allocation-free scratch)
// ---------------------------------------------------------------------------
__device__ __align__(256) float g_xproj[(size_t)S_ * B_ * H_];        // [m=s*B+b][h]
__device__ __align__(256) float g_hf[B_ * H_];                        // fp32 final h
__device__ __align__(256) __nv_bfloat16 g_hbf[2][2][B_ * H_];         // [pingpong][hi/lo][b][k]
__device__ __align__(256) __nv_bfloat16 g_xr[2][(size_t)S_ * B_ * I_];// [hi/lo][m=s*B+b][i]
__device__ __align__(256) __nv_bfloat16 g_Wxbf[2][(size_t)H_ * I_];   // [hi/lo][h][i]
__device__ unsigned g_flag[4][4];   // [bt][kslice]: 8 producer arrivals per step

// ---------------------------------------------------------------------------
// helpers
// ---------------------------------------------------------------------------
__device__ __forceinline__ void cp_async16(void* s, const void* g) {
    uint32_t sa = (uint32_t)__cvta_generic_to_shared(s);
    asm volatile("cp.async.cg.shared.global [%0], [%1], 16;" :: "r"(sa), "l"(g));
}
__device__ __forceinline__ void cp_commit() { asm volatile("cp.async.commit_group;"); }
template <int N> __device__ __forceinline__ void cp_wait() {
    asm volatile("cp.async.wait_group %0;" :: "n"(N));
}
__device__ __forceinline__ uint32_t sptr(const void* p) {
    return (uint32_t)__cvta_generic_to_shared(p);
}
__device__ __forceinline__ void ldsm_x4(uint32_t& r0, uint32_t& r1, uint32_t& r2, uint32_t& r3,
                                        uint32_t addr) {
    asm volatile("ldmatrix.sync.aligned.m8n8.x4.shared.b16 {%0,%1,%2,%3}, [%4];"
                 : "=r"(r0), "=r"(r1), "=r"(r2), "=r"(r3) : "r"(addr));
}
__device__ __forceinline__ void mma_bf16(float& c0, float& c1, float& c2, float& c3,
                                         uint32_t a0, uint32_t a1, uint32_t a2, uint32_t a3,
                                         uint32_t b0, uint32_t b1) {
    asm volatile("mma.sync.aligned.m16n8k16.row.col.f32.bf16.bf16.f32 "
                 "{%0,%1,%2,%3}, {%4,%5,%6,%7}, {%8,%9}, {%0,%1,%2,%3};"
                 : "+f"(c0), "+f"(c1), "+f"(c2), "+f"(c3)
                 : "r"(a0), "r"(a1), "r"(a2), "r"(a3), "r"(b0), "r"(b1));
}
__device__ __forceinline__ void fma4(float4& acc, const float4 a, const float4 b) {
    acc.x = fmaf(a.x, b.x, acc.x);
    acc.y = fmaf(a.y, b.y, acc.y);
    acc.z = fmaf(a.z, b.z, acc.z);
    acc.w = fmaf(a.w, b.w, acc.w);
}
__device__ __forceinline__ void split2(float v, __nv_bfloat16& hi, __nv_bfloat16& lo) {
    hi = __float2bfloat16(v);
    lo = __float2bfloat16(v - __bfloat162float(hi));
}
__device__ __forceinline__ void bar_arrive(unsigned* p) {
    asm volatile("red.release.gpu.global.add.u32 [%0], 1;" :: "l"(p) : "memory");
}
__device__ __forceinline__ void bar_wait(unsigned* p, unsigned target) {
    unsigned v;
    do {
        asm volatile("ld.acquire.gpu.global.u32 %0, [%1];" : "=r"(v) : "l"(p) : "memory");
    } while ((int)(v - target) < 0);
}
__device__ __forceinline__ uint32_t cl_rank() {
    uint32_t r;
    asm("mov.u32 %0, %%cluster_ctarank;" : "=r"(r));
    return r;
}
#define MBAR_INIT(mbar, cnt) \
    asm volatile("mbarrier.init.shared.b64 [%0], %1;" :: "r"(mbar), "r"(cnt) : "memory")
#define MBAR_EXPECT(mbar, tx) \
    asm volatile("mbarrier.arrive.expect_tx.shared.b64 _, [%0], %1;" :: "r"(mbar), "r"(tx) : "memory")
#define MBAR_WAIT(mbar, ph) do {                                              \
    uint32_t _done = 0;                                                       \
    while (!_done) {                                                          \
        asm volatile("{\n\t.reg .pred p;\n\t"                                 \
                     "mbarrier.try_wait.parity.acquire.cta.shared::cta.b64 p, [%1], %2;\n\t" \
                     "selp.b32 %0, 1, 0, p;\n\t}"                             \
                     : "=r"(_done) : "r"(mbar), "r"(ph) : "memory");          \
    }                                                                         \
} while (0)
#define MBAR_ARRIVE_RANK(local_mbar, rankv)                                   \
    asm volatile("{\n\t.reg .b32 ra;\n\t"                                     \
                 "mapa.shared::cluster.u32 ra, %0, %1;\n\t"                   \
                 "mbarrier.arrive.release.cluster.shared::cluster.b64 _, [ra];\n\t}" \
                 :: "r"(local_mbar), "r"(rankv) : "memory")
#define BULK_MC(dst, src, bytes, mbar, mask) \
    asm volatile("cp.async.bulk.shared::cluster.global.mbarrier::complete_tx::bytes.multicast::cluster " \
                 "[%0], [%1], %2, [%3], %4;" \
                 :: "r"(dst), "l"(src), "r"(bytes), "r"(mbar), "h"((uint16_t)(mask)) : "memory")
#define CLUSTER_SYNC_() do { \
    asm volatile("barrier.cluster.arrive.aligned;" ::: "memory"); \
    asm volatile("barrier.cluster.wait.aligned;" ::: "memory"); \
} while (0)

// ---------------------------------------------------------------------------
// conversions: x -> reordered hi/lo bf16 [m=s*B+b][i]; Wx -> hi/lo
// ---------------------------------------------------------------------------
__global__ __launch_bounds__(256) void k_convert_x(const float* __restrict__ x) {
    int gid = blockIdx.x * blockDim.x + threadIdx.x;   // S*B*I/4 units
    if (gid < 16) ((unsigned*)g_flag)[gid] = 0;        // reset flags each launch
    int i4 = (gid & (I_ / 4 - 1)) * 4;
    int m  = gid >> 7;                                 // I_/4 = 128
    int s = m / B_, b = m % B_;
    float4 v = *(const float4*)(x + ((size_t)b * S_ + s) * I_ + i4);
    __nv_bfloat16 h0, l0, h1, l1, h2, l2, h3, l3;
    split2(v.x, h0, l0); split2(v.y, h1, l1);
    split2(v.z, h2, l2); split2(v.w, h3, l3);
    __nv_bfloat162 p;
    __nv_bfloat16* dh = g_xr[0] + (size_t)m * I_ + i4;
    __nv_bfloat16* dl = g_xr[1] + (size_t)m * I_ + i4;
    p.x = h0; p.y = h1; *(__nv_bfloat162*)(dh)     = p;
    p.x = h2; p.y = h3; *(__nv_bfloat162*)(dh + 2) = p;
    p.x = l0; p.y = l1; *(__nv_bfloat162*)(dl)     = p;
    p.x = l2; p.y = l3; *(__nv_bfloat162*)(dl + 2) = p;
}

__global__ __launch_bounds__(256) void k_convert_wx(const float* __restrict__ Wx) {
    int gid = blockIdx.x * blockDim.x + threadIdx.x;   // H*I/4 units
    int i = gid * 4;
    float4 v = *(const float4*)(Wx + i);
    __nv_bfloat16 h0, l0, h1, l1, h2, l2, h3, l3;
    split2(v.x, h0, l0); split2(v.y, h1, l1);
    split2(v.z, h2, l2); split2(v.w, h3, l3);
    __nv_bfloat162 p;
    p.x = h0; p.y = h1; *(__nv_bfloat162*)(g_Wxbf[0] + i)     = p;
    p.x = h2; p.y = h3; *(__nv_bfloat162*)(g_Wxbf[0] + i + 2) = p;
    p.x = l0; p.y = l1; *(__nv_bfloat162*)(g_Wxbf[1] + i)     = p;
    p.x = l2; p.y = l3; *(__nv_bfloat162*)(g_Wxbf[1] + i + 2) = p;
}

// ---------------------------------------------------------------------------
// xproj GEMM via bf16x2-split mma (unchanged)
// ---------------------------------------------------------------------------
#define XKC  64
#define XPA  72

__global__ __launch_bounds__(256) void k_xproj_mma(const float* __restrict__ bx) {
    extern __shared__ __nv_bfloat16 dsm[];
    __nv_bfloat16* sa = dsm;
    __nv_bfloat16* sb = dsm + 2 * 2 * 128 * XPA;

    const int tid = threadIdx.x;
    const int lane = tid & 31, wid = tid >> 5;
    const int n0 = blockIdx.x * 64;
    const int m0 = blockIdx.y * 128;
    const int wm = (wid & 3) * 32;
    const int wn = (wid >> 2) * 32;

    float acc[2][4][4];
#pragma unroll
    for (int a = 0; a < 2; a++)
#pragma unroll
        for (int b = 0; b < 4; b++)
#pragma unroll
            for (int c = 0; c < 4; c++) acc[a][b][c] = 0.0f;

    auto load_chunk = [&](int buf, int k0) {
#pragma unroll
        for (int sp = 0; sp < 2; sp++) {
            __nv_bfloat16* da = sa + (size_t)(buf * 2 + sp) * 128 * XPA;
            const __nv_bfloat16* ga = g_xr[sp];
#pragma unroll
            for (int q = 0; q < 4; q++) {
                int u = tid + q * 256;
                int row = u >> 3, c16 = (u & 7) * 8;
                cp_async16(da + row * XPA + c16,
                           ga + (size_t)(m0 + row) * I_ + k0 + c16);
            }
            __nv_bfloat16* db = sb + (size_t)(buf * 2 + sp) * 64 * XPA;
            const __nv_bfloat16* gb = g_Wxbf[sp];
#pragma unroll
            for (int q = 0; q < 2; q++) {
                int u = tid + q * 256;
                int row = u >> 3, c16 = (u & 7) * 8;
                cp_async16(db + row * XPA + c16,
                           gb + (size_t)(n0 + row) * I_ + k0 + c16);
            }
        }
        cp_commit();
    };

    load_chunk(0, 0);

    const int a_row  = wm + (lane & 15);
    const int a_koff = (lane >> 4) * 8;
    const int b_row  = wn + ((lane >> 4) * 8) + (lane & 7);
    const int b_koff = ((lane >> 3) & 1) * 8;

    for (int ch = 0; ch < I_ / XKC; ch++) {
        if (ch + 1 < I_ / XKC) { load_chunk((ch + 1) & 1, (ch + 1) * XKC); cp_wait<1>(); }
        else                   { cp_wait<0>(); }
        __syncthreads();
        const int buf = ch & 1;
        const __nv_bfloat16* ah_base = sa + (size_t)(buf * 2 + 0) * 128 * XPA;
        const __nv_bfloat16* al_base = sa + (size_t)(buf * 2 + 1) * 128 * XPA;
        const __nv_bfloat16* bh_base = sb + (size_t)(buf * 2 + 0) * 64 * XPA;
        const __nv_bfloat16* bl_base = sb + (size_t)(buf * 2 + 1) * 64 * XPA;
#pragma unroll
        for (int kk = 0; kk < XKC; kk += 16) {
            uint32_t ah[2][4], al[2][4];
#pragma unroll
            for (int fm = 0; fm < 2; fm++) {
                ldsm_x4(ah[fm][0], ah[fm][1], ah[fm][2], ah[fm][3],
                        sptr(ah_base + (a_row + fm * 16) * XPA + kk + a_koff));
                ldsm_x4(al[fm][0], al[fm][1], al[fm][2], al[fm][3],
                        sptr(al_base + (a_row + fm * 16) * XPA + kk + a_koff));
            }
            uint32_t bh[2][4], bl[2][4];
#pragma unroll
            for (int g = 0; g < 2; g++) {
                ldsm_x4(bh[g][0], bh[g][1], bh[g][2], bh[g][3],
                        sptr(bh_base + (b_row + g * 16) * XPA + kk + b_koff));
                ldsm_x4(bl[g][0], bl[g][1], bl[g][2], bl[g][3],
                        sptr(bl_base + (b_row + g * 16) * XPA + kk + b_koff));
            }
#pragma unroll
            for (int fm = 0; fm < 2; fm++)
#pragma unroll
                for (int fn = 0; fn < 4; fn++) {
                    int g = fn >> 1, o = (fn & 1) * 2;
                    float* c = acc[fm][fn];
                    mma_bf16(c[0], c[1], c[2], c[3],
                             ah[fm][0], ah[fm][1], ah[fm][2], ah[fm][3],
                             bh[g][o], bh[g][o + 1]);
                    mma_bf16(c[0], c[1], c[2], c[3],
                             ah[fm][0], ah[fm][1], ah[fm][2], ah[fm][3],
                             bl[g][o], bl[g][o + 1]);
                    mma_bf16(c[0], c[1], c[2], c[3],
                             al[fm][0], al[fm][1], al[fm][2], al[fm][3],
                             bh[g][o], bh[g][o + 1]);
                }
        }
        __syncthreads();
    }

    const int r = lane >> 2;
    const int cp = (lane & 3) * 2;
#pragma unroll
    for (int fn = 0; fn < 4; fn++) {
        int col = n0 + wn + fn * 8 + cp;
        float2 bias = *(const float2*)(bx + col);
#pragma unroll
        for (int fm = 0; fm < 2; fm++) {
            int mr = m0 + wm + fm * 16 + r;
            float2 v0 = make_float2(acc[fm][fn][0] + bias.x, acc[fm][fn][1] + bias.y);
            float2 v1 = make_float2(acc[fm][fn][2] + bias.x, acc[fm][fn][3] + bias.y);
            *(float2*)(g_xproj + (size_t)mr * H_ + col) = v0;
            *(float2*)(g_xproj + (size_t)(mr + 8) * H_ + col) = v1;
        }
    }
}

// ---------------------------------------------------------------------------
// Persistent recurrence kernel v6: 512 threads = 4 n-warps x 4 K-quarter
// groups. Cluster-4 multicast h exchange; per-slice flags + mbars; per-CTA
// 'free' mbar (4 cluster arrivals) gates plane overwrite (race fix).
// ---------------------------------------------------------------------------
#define PIT  264   // halves per SMEM row (256 + 8), 528B pitch
#define REDP 33    // red row pitch (floats)
#define PLANE_BYTES (32 * PIT * 2)
#define SMEM_PLANES (8 * 32 * PIT)                     // halves
#define RED_OFF_B   (SMEM_PLANES * 2)                  // bytes
#define MBAR_OFF_B  (RED_OFF_B + 4 * 32 * REDP * 4)    // bytes (8-aligned)

__global__ __launch_bounds__(512, 1) __cluster_dims__(4, 1, 1)
void k_rnn(const float* __restrict__ Wh) {
    extern __shared__ __nv_bfloat16 dsm[];
    float* red = (float*)((char*)dsm + RED_OFF_B);     // [4][32][REDP]
    uint32_t mb0  = sptr((char*)dsm + MBAR_OFF_B);     // 4 data mbars (per slice)
    uint32_t mbfr = mb0 + 4 * 8;                       // 1 'free' mbar

    const int tid = threadIdx.x;
    const int lane = tid & 31, wid = tid >> 5;
    const int ks4 = wid >> 2;         // K-quarter group = k-slice
    const int nw = wid & 3;           // n-warp (8 j-cols)
    const int gtid = tid & 127;
    const int jt = blockIdx.x & 31, bt = blockIdx.x >> 5;
    const int jb = jt * 32, bb = bt * 32;
    const uint32_t rank = cl_rank();

    if (tid == 0) {
#pragma unroll
        for (int i = 0; i < 4; i++) MBAR_INIT(mb0 + i * 8, 1);
        MBAR_INIT(mbfr, 4);
    }
    __syncthreads();
    CLUSTER_SYNC_();   // peers' barriers live before any multicast targets them

    // --- stage this group's Wh k-slice (32 rows x 256 cols, hi/lo) ---
    {
        const int kbase = ks4 * 256;
        __nv_bfloat16* dh = dsm + (ks4 * 2 + 0) * 32 * PIT;
        __nv_bfloat16* dl = dsm + (ks4 * 2 + 1) * 32 * PIT;
#pragma unroll
        for (int q = 0; q < 16; q++) {
            int u = gtid + q * 128;
            int row = u >> 6;
            int c4 = (u & 63) * 4;
            float4 v = *(const float4*)(Wh + (size_t)(jb + row) * H_ + kbase + c4);
            __nv_bfloat16 h0, l0, h1, l1, h2, l2, h3, l3;
            split2(v.x, h0, l0); split2(v.y, h1, l1);
            split2(v.z, h2, l2); split2(v.w, h3, l3);
            __nv_bfloat16* ph = dh + row * PIT + c4;
            __nv_bfloat16* pl = dl + row * PIT + c4;
            ph[0] = h0; ph[1] = h1; ph[2] = h2; ph[3] = h3;
            pl[0] = l0; pl[1] = l1; pl[2] = l2; pl[3] = l3;
        }
    }
    __syncthreads();

    // --- register-resident Wh fragments (n8 x K256 per warp) ---
    const int b_row  = nw * 8 + (lane & 7);
    const int b_koff = (lane >> 3) * 8;
    uint32_t bfh[8][4], bfl[8][4];
    {
        const __nv_bfloat16* ph = dsm + (ks4 * 2 + 0) * 32 * PIT;
        const __nv_bfloat16* pl = dsm + (ks4 * 2 + 1) * 32 * PIT;
#pragma unroll
        for (int g = 0; g < 8; g++) {
            int col = g * 32 + b_koff;
            ldsm_x4(bfh[g][0], bfh[g][1], bfh[g][2], bfh[g][3], sptr(ph + b_row * PIT + col));
            ldsm_x4(bfl[g][0], bfl[g][1], bfl[g][2], bfl[g][3], sptr(pl + b_row * PIT + col));
        }
    }
    __syncthreads();

    // epilogue mapping (512 threads, 2 outputs each)
    const int erow = tid >> 4;          // 0..31
    const int ecol = (tid & 15) * 2;    // 0..30

    // --- t = 0: h(1) = tanh(xproj[0]) ---
    {
        float2 v = *(const float2*)(g_xproj + (size_t)(bb + erow) * H_ + jb + ecol);
        float t0 = tanhf(v.x), t1 = tanhf(v.y);
        __nv_bfloat16 h0, l0, h1, l1;
        split2(t0, h0, l0); split2(t1, h1, l1);
        __nv_bfloat162 p;
        p.x = h0; p.y = h1;
        *(__nv_bfloat162*)(g_hbf[1][0] + (size_t)(bb + erow) * H_ + jb + ecol) = p;
        p.x = l0; p.y = l1;
        *(__nv_bfloat162*)(g_hbf[1][1] + (size_t)(bb + erow) * H_ + jb + ecol) = p;
    }
    __syncthreads();
    if (tid == 0) bar_arrive(&g_flag[bt][jt >> 3]);
    if (tid < 4) MBAR_ARRIVE_RANK(mbfr, tid);   // planes free for step-1 copies

    const int a_row  = lane & 15;
    const int a_koff = (lane >> 4) * 8;
    const int srow = lane >> 2;
    const int scol = nw * 8 + (lane & 3) * 2;

    // copy role: warp wid -> slice f=ks4, q=nw: plane = f*2 + (q>>1),
    // rows rank*8 + (q&1)*4 .. +4
    const int cq   = nw;
    const int cpl  = ks4 * 2 + (cq >> 1);
    const int csp  = cq >> 1;                 // hi/lo
    const int crow = (cq & 1) * 4;
    const uint32_t idst0 = sptr((char*)dsm + (size_t)cpl * PLANE_BYTES)
                         + (rank * 8 + crow) * PIT * 2;
    const uint32_t imbar = mb0 + ks4 * 8;
    unsigned* iflag = &g_flag[bt][ks4];

    for (int t = 1; t < S_; t++) {
        // independent prefetch fills the wait shadow
        const float* xp = g_xproj + (size_t)t * B_ * H_;
        float2 xv = __ldg((const float2*)(xp + (size_t)(bb + erow) * H_ + jb + ecol));

        const uint32_t ph_par = (unsigned)(t - 1) & 1u;

        // copy phase: wait planes free (cluster) + slice producers, then ship
        if (lane == 0) {
            MBAR_WAIT(mbfr, ph_par);
            bar_wait(iflag, 8u * (unsigned)t);
            if (cq == 0) MBAR_EXPECT(imbar, 32768u);
            const __nv_bfloat16* src = g_hbf[t & 1][csp];
            const size_t base = (size_t)(bb + rank * 8 + crow) * H_ + ks4 * 256;
#pragma unroll
            for (int rrow = 0; rrow < 4; rrow++) {
                BULK_MC(idst0 + rrow * PIT * 2,
                        src + base + (size_t)rrow * H_,
                        512u, imbar, 0xFu);
            }
        }

        float c1[2][4] = {0}, c2[2][4] = {0}, c3[2][4] = {0};

        // consume this group's slice
        MBAR_WAIT(imbar, ph_par);
        {
            const __nv_bfloat16* ph = dsm + (ks4 * 2 + 0) * 32 * PIT;
            const __nv_bfloat16* pl = dsm + (ks4 * 2 + 1) * 32 * PIT;
#pragma unroll
            for (int g = 0; g < 8; g++) {
                const int cb = g * 32;
#pragma unroll
                for (int kh = 0; kh < 2; kh++) {
                    uint32_t ah[2][4], al[2][4];
#pragma unroll
                    for (int fm = 0; fm < 2; fm++) {
                        ldsm_x4(ah[fm][0], ah[fm][1], ah[fm][2], ah[fm][3],
                                sptr(ph + (a_row + fm * 16) * PIT + cb + kh * 16 + a_koff));
                        ldsm_x4(al[fm][0], al[fm][1], al[fm][2], al[fm][3],
                                sptr(pl + (a_row + fm * 16) * PIT + cb + kh * 16 + a_koff));
                    }
#pragma unroll
                    for (int fm = 0; fm < 2; fm++) {
                        mma_bf16(c1[fm][0], c1[fm][1], c1[fm][2], c1[fm][3],
                                 ah[fm][0], ah[fm][1], ah[fm][2], ah[fm][3],
                                 bfh[g][kh * 2], bfh[g][kh * 2 + 1]);
                        mma_bf16(c2[fm][0], c2[fm][1], c2[fm][2], c2[fm][3],
                                 ah[fm][0], ah[fm][1], ah[fm][2], ah[fm][3],
                                 bfl[g][kh * 2], bfl[g][kh * 2 + 1]);
                        mma_bf16(c3[fm][0], c3[fm][1], c3[fm][2], c3[fm][3],
                                 al[fm][0], al[fm][1], al[fm][2], al[fm][3],
                                 bfh[g][kh * 2], bfh[g][kh * 2 + 1]);
                    }
                }
            }
        }

        // scatter partial sums to SMEM red[ks4]
        float* rb = red + ks4 * 32 * REDP;
#pragma unroll
        for (int fm = 0; fm < 2; fm++) {
            float s0 = c1[fm][0] + c2[fm][0] + c3[fm][0];
            float s1 = c1[fm][1] + c2[fm][1] + c3[fm][1];
            float s2 = c1[fm][2] + c2[fm][2] + c3[fm][2];
            float s3 = c1[fm][3] + c2[fm][3] + c3[fm][3];
            rb[(fm * 16 + srow) * REDP + scol]     = s0;
            rb[(fm * 16 + srow) * REDP + scol + 1] = s1;
            rb[(fm * 16 + 8 + srow) * REDP + scol]     = s2;
            rb[(fm * 16 + 8 + srow) * REDP + scol + 1] = s3;
        }
        __syncthreads();
        // all plane reads in this CTA retired -> planes free for next copies
        if (tid < 4 && t < S_ - 1) MBAR_ARRIVE_RANK(mbfr, tid);

        // cooperative epilogue: 2 outputs per thread
        {
            const float* r0 = red + erow * REDP + ecol;
            float z0 = r0[0] + xv.x;
            float z1 = r0[1] + xv.y;
#pragma unroll
            for (int q = 1; q < 4; q++) {
                z0 += r0[q * 32 * REDP];
                z1 += r0[q * 32 * REDP + 1];
            }
            z0 = tanhf(z0);
            z1 = tanhf(z1);

            if (t < S_ - 1) {
                __nv_bfloat16 h0, l0, h1, l1;
                split2(z0, h0, l0); split2(z1, h1, l1);
                __nv_bfloat162 p;
                p.x = h0; p.y = h1;
                *(__nv_bfloat162*)(g_hbf[(t + 1) & 1][0] + (size_t)(bb + erow) * H_ + jb + ecol) = p;
                p.x = l0; p.y = l1;
                *(__nv_bfloat162*)(g_hbf[(t + 1) & 1][1] + (size_t)(bb + erow) * H_ + jb + ecol) = p;
            } else {
                *(float2*)(g_hf + (size_t)(bb + erow) * H_ + jb + ecol) = make_float2(z0, z1);
            }
        }
        __syncthreads();
        if (tid == 0 && t < S_ - 1) bar_arrive(&g_flag[bt][jt >> 3]);
    }
    CLUSTER_SYNC_();   // no CTA exits while peers' multicasts may target it
}

// ---------------------------------------------------------------------------
// Final projection (fp32 SIMT, tiny)
// ---------------------------------------------------------------------------
#define KC   64
#define SROW (KC + 4)

__global__ __launch_bounds__(256) void k_final(const float* __restrict__ Wp,
                                               const float* __restrict__ bp,
                                               float* __restrict__ out) {
    __shared__ float hs[2][32][SROW];
    __shared__ float ws[2][32][SROW];
    const int tid = threadIdx.x;
    const int jb = blockIdx.x * 32;
    const int bb = blockIdx.y * 32;
    const float* __restrict__ hin = g_hf;

    const int r0 = tid >> 4;
    const int c0 = (tid & 15) << 2;

    float4 acc00 = {0,0,0,0}, acc01 = {0,0,0,0}, acc10 = {0,0,0,0}, acc11 = {0,0,0,0};
    const int b0 = (tid >> 4) << 1;
    const int j0 = tid & 15;

    {
#pragma unroll
        for (int q = 0; q < 2; q++) {
            int row = r0 + q * 16;
            cp_async16(&hs[0][row][c0], hin + (size_t)(bb + row) * H_ + c0);
            cp_async16(&ws[0][row][c0], Wp  + (size_t)(jb + row) * H_ + c0);
        }
        cp_commit();
    }

    for (int c = 0; c < H_ / KC; c++) {
        if (c + 1 < H_ / KC) {
            int k0 = (c + 1) * KC;
            int nb = (c + 1) & 1;
#pragma unroll
            for (int q = 0; q < 2; q++) {
                int row = r0 + q * 16;
                cp_async16(&hs[nb][row][c0], hin + (size_t)(bb + row) * H_ + k0 + c0);
                cp_async16(&ws[nb][row][c0], Wp  + (size_t)(jb + row) * H_ + k0 + c0);
            }
            cp_commit();
            cp_wait<1>();
        } else {
            cp_wait<0>();
        }
        __syncthreads();
        const int buf = c & 1;
#pragma unroll
        for (int k4 = 0; k4 < KC; k4 += 4) {
            float4 a0 = *(const float4*)&hs[buf][b0    ][k4];
            float4 a1 = *(const float4*)&hs[buf][b0 + 1][k4];
            float4 w0 = *(const float4*)&ws[buf][j0     ][k4];
            float4 w1 = *(const float4*)&ws[buf][j0 + 16][k4];
            fma4(acc00, a0, w0); fma4(acc01, a0, w1);
            fma4(acc10, a1, w0); fma4(acc11, a1, w1);
        }
        __syncthreads();
    }

    {
        int bg = bb + b0, jg = jb + j0;
        float z;
        z = (acc00.x + acc00.y) + (acc00.z + acc00.w) + bp[jg];
        out[(size_t)bg * O_ + jg] = z;
        z = (acc01.x + acc01.y) + (acc01.z + acc01.w) + bp[jg + 16];
        out[(size_t)bg * O_ + jg + 16] = z;
        z = (acc10.x + acc10.y) + (acc10.z + acc10.w) + bp[jg];
        out[(size_t)(bg + 1) * O_ + jg] = z;
        z = (acc11.x + acc11.y) + (acc11.z + acc11.w) + bp[jg + 16];
        out[(size_t)(bg + 1) * O_ + jg + 16] = z;
    }
}

// ---------------------------------------------------------------------------
// launch
// ---------------------------------------------------------------------------
extern "C" void kernel_launch(void* const* d_in, const int* in_sizes, int n_in,
                              void* d_out, int out_size) {
    const float* x  = (const float*)d_in[0];
    const float* Wx = (const float*)d_in[1];
    const float* bx = (const float*)d_in[2];
    const float* Wh = (const float*)d_in[3];
    const float* Wp = (const float*)d_in[4];
    const float* bp = (const float*)d_in[5];
    float* out = (float*)d_out;

    const int XSMEM = (2 * 2 * 128 * XPA + 2 * 2 * 64 * XPA) * (int)sizeof(__nv_bfloat16);
    const int RSMEM = MBAR_OFF_B + 5 * 8;
    cudaFuncSetAttribute(k_xproj_mma, cudaFuncAttributeMaxDynamicSharedMemorySize, XSMEM);
    cudaFuncSetAttribute(k_rnn, cudaFuncAttributeMaxDynamicSharedMemorySize, RSMEM);

    k_convert_x<<<(S_ * B_ * I_ / 4) / 256, 256>>>(x);
    k_convert_wx<<<(H_ * I_ / 4) / 256, 256>>>(Wx);
    k_xproj_mma<<<dim3(H_ / 64, (B_ * S_) / 128), 256, XSMEM>>>(bx);
    k_rnn<<<NCTA, 512, RSMEM>>>(Wh);
    k_final<<<dim3(O_ / 32, B_ / 32), 256>>>(Wp, bp, out);
}